// round 1
// baseline (speedup 1.0000x reference)
#include <cuda_runtime.h>
#include <math.h>
#include <stdint.h>

// ---------------------------------------------------------------------------
// Problem constants
// ---------------------------------------------------------------------------
#define B_SZ    2
#define LSEQ    2048
#define DMODEL  1024
#define DINNER  2048
#define DSTATE  16
#define DTRANK  64
#define DCONV   4
#define M_ROWS  (B_SZ * LSEQ)            // 4096
#define XZ_COLS (2 * DINNER)             // 4096
#define XDBL_COLS (DTRANK + 2 * DSTATE)  // 96

// ---------------------------------------------------------------------------
// Scratch (static device allocations: no cudaMalloc allowed)
// ---------------------------------------------------------------------------
__device__ float g_xz  [(size_t)M_ROWS * XZ_COLS];    // in_proj output [4096,4096]
__device__ float g_xc  [(size_t)M_ROWS * DINNER];     // conv+silu     [4096,2048]
__device__ float g_xdbl[(size_t)M_ROWS * XDBL_COLS];  // x_proj output [4096,96]
__device__ float g_dt  [(size_t)M_ROWS * DINNER];     // softplus(dt)  [4096,2048]
__device__ float g_y   [(size_t)M_ROWS * DINNER];     // scan output   [4096,2048]

// ---------------------------------------------------------------------------
// Generic NT SGEMM: C[M,N] = A[M,K] * B[N,K]^T   (both row-major, K contiguous)
// EPI: 0 = plain store, 1 = softplus(acc + bias[col])
// Requires M%BM==0, N%BN==0, K%BK==0, and 16B-aligned rows (lda/ldb %4==0).
// ---------------------------------------------------------------------------
template<int BM, int BN, int BK, int TM, int TN, int EPI>
__global__ void sgemm_nt(int M, int N, int K,
                         const float* __restrict__ A, int lda,
                         const float* __restrict__ Bm, int ldb,
                         float* __restrict__ C, int ldc,
                         const float* __restrict__ bias)
{
    constexpr int THREADS = (BM / TM) * (BN / TN);
    __shared__ float As[BK][BM];
    __shared__ float Bs[BK][BN];

    const int tid  = threadIdx.x;
    const int brow = blockIdx.y * BM;
    const int bcol = blockIdx.x * BN;
    const int tcol = tid % (BN / TN);
    const int trow = tid / (BN / TN);

    float acc[TM][TN];
#pragma unroll
    for (int i = 0; i < TM; i++)
#pragma unroll
        for (int j = 0; j < TN; j++) acc[i][j] = 0.f;

    constexpr int AV = (BM * BK) / (4 * THREADS);  // float4 loads/thread for A
    constexpr int BV = (BN * BK) / (4 * THREADS);
    constexpr int ROWS_PER_PASS = (THREADS * 4) / BK;
    const int l_r = (tid * 4) / BK;
    const int l_c = (tid * 4) % BK;

    for (int k0 = 0; k0 < K; k0 += BK) {
#pragma unroll
        for (int v = 0; v < AV; v++) {
            int r = l_r + v * ROWS_PER_PASS;
            float4 f = *reinterpret_cast<const float4*>(
                &A[(size_t)(brow + r) * lda + k0 + l_c]);
            As[l_c + 0][r] = f.x; As[l_c + 1][r] = f.y;
            As[l_c + 2][r] = f.z; As[l_c + 3][r] = f.w;
        }
#pragma unroll
        for (int v = 0; v < BV; v++) {
            int r = l_r + v * ROWS_PER_PASS;
            float4 f = *reinterpret_cast<const float4*>(
                &Bm[(size_t)(bcol + r) * ldb + k0 + l_c]);
            Bs[l_c + 0][r] = f.x; Bs[l_c + 1][r] = f.y;
            Bs[l_c + 2][r] = f.z; Bs[l_c + 3][r] = f.w;
        }
        __syncthreads();

#pragma unroll
        for (int k = 0; k < BK; k++) {
            float ar[TM], br[TN];
#pragma unroll
            for (int i = 0; i < TM; i++) ar[i] = As[k][trow * TM + i];
#pragma unroll
            for (int j = 0; j < TN; j++) br[j] = Bs[k][tcol * TN + j];
#pragma unroll
            for (int i = 0; i < TM; i++)
#pragma unroll
                for (int j = 0; j < TN; j++)
                    acc[i][j] += ar[i] * br[j];
        }
        __syncthreads();
    }

#pragma unroll
    for (int i = 0; i < TM; i++) {
        int r = brow + trow * TM + i;
#pragma unroll
        for (int j = 0; j < TN; j++) {
            int c = bcol + tcol * TN + j;
            float v = acc[i][j];
            if (EPI == 1) {
                v += bias[c];
                v = (v > 20.f) ? v : log1pf(__expf(v));  // softplus
            }
            C[(size_t)r * ldc + c] = v;
        }
    }
}

// ---------------------------------------------------------------------------
// Depthwise causal conv1d (taps=4) + bias + SiLU, reading the x-branch half
// of g_xz.  One thread per (b, t, d) output element.
// ---------------------------------------------------------------------------
__global__ void conv_silu_kernel(const float* __restrict__ conv_w,
                                 const float* __restrict__ conv_b)
{
    int idx = blockIdx.x * blockDim.x + threadIdx.x;   // over 8M
    if (idx >= M_ROWS * DINNER) return;
    int d = idx % DINNER;
    int m = idx / DINNER;       // b*L + t
    int t = m % LSEQ;
    int b = m / LSEQ;

    float acc = conv_b[d];
#pragma unroll
    for (int j = 0; j < DCONV; j++) {
        int tt = t - (DCONV - 1) + j;
        if (tt >= 0)
            acc += g_xz[(size_t)(b * LSEQ + tt) * XZ_COLS + d] * conv_w[d * DCONV + j];
    }
    float s = 1.f / (1.f + __expf(-acc));
    g_xc[(size_t)m * DINNER + d] = acc * s;            // silu
}

// ---------------------------------------------------------------------------
// Selective scan.  16 lanes per channel (one lane per state n).
// Block = 256 threads = 16 channels.  Grid = B*DINNER/16 = 256 blocks.
// ---------------------------------------------------------------------------
__global__ void scan_kernel(const float* __restrict__ A_log,
                            const float* __restrict__ D_param)
{
    const int lane16 = threadIdx.x & 15;
    const int grp    = threadIdx.x >> 4;
    const int chunk  = blockIdx.x;                 // 0 .. B*DINNER/16-1
    const int b      = chunk / (DINNER / 16);
    const int d      = (chunk % (DINNER / 16)) * 16 + grp;

    const float Ad = -__expf(A_log[d * DSTATE + lane16]);
    const float Dd = D_param[d];

    const float* dt_p = g_dt   + (size_t)b * LSEQ * DINNER + d;
    const float* x_p  = g_xc   + (size_t)b * LSEQ * DINNER + d;
    const float* bc_p = g_xdbl + (size_t)b * LSEQ * XDBL_COLS;
    float*       y_p  = g_y    + (size_t)b * LSEQ * DINNER + d;

    float h = 0.f;
    // prefetch t = 0
    float dtv = dt_p[0];
    float xv  = x_p[0];
    float Bv  = bc_p[DTRANK + lane16];
    float Cv  = bc_p[DTRANK + DSTATE + lane16];

    for (int t = 0; t < LSEQ; t++) {
        float ndt = 0.f, nx = 0.f, nB = 0.f, nC = 0.f;
        if (t + 1 < LSEQ) {
            ndt = dt_p[(size_t)(t + 1) * DINNER];
            nx  = x_p [(size_t)(t + 1) * DINNER];
            nB  = bc_p[(size_t)(t + 1) * XDBL_COLS + DTRANK + lane16];
            nC  = bc_p[(size_t)(t + 1) * XDBL_COLS + DTRANK + DSTATE + lane16];
        }
        float dA = __expf(dtv * Ad);
        h = dA * h + (dtv * xv) * Bv;
        float p = h * Cv;
        p += __shfl_xor_sync(0xffffffffu, p, 1);
        p += __shfl_xor_sync(0xffffffffu, p, 2);
        p += __shfl_xor_sync(0xffffffffu, p, 4);
        p += __shfl_xor_sync(0xffffffffu, p, 8);
        if (lane16 == 0)
            y_p[(size_t)t * DINNER] = p + Dd * xv;
        dtv = ndt; xv = nx; Bv = nB; Cv = nC;
    }
}

// ---------------------------------------------------------------------------
// Gate: y *= silu(z)   (z = second half of g_xz), in place on g_y.
// ---------------------------------------------------------------------------
__global__ void gate_kernel()
{
    int idx = blockIdx.x * blockDim.x + threadIdx.x;   // over 8M
    if (idx >= M_ROWS * DINNER) return;
    int d = idx % DINNER;
    int m = idx / DINNER;
    float z = g_xz[(size_t)m * XZ_COLS + DINNER + d];
    float s = z / (1.f + __expf(-z));                  // silu
    g_y[(size_t)m * DINNER + d] *= s;
}

// ---------------------------------------------------------------------------
// Launch
// ---------------------------------------------------------------------------
extern "C" void kernel_launch(void* const* d_in, const int* in_sizes, int n_in,
                              void* d_out, int out_size)
{
    const float* x         = (const float*)d_in[0];
    const float* in_proj_w = (const float*)d_in[1];
    const float* conv_w    = (const float*)d_in[2];
    const float* conv_b    = (const float*)d_in[3];
    const float* x_proj_w  = (const float*)d_in[4];
    const float* dt_proj_w = (const float*)d_in[5];
    const float* dt_proj_b = (const float*)d_in[6];
    const float* A_log     = (const float*)d_in[7];
    const float* D_param   = (const float*)d_in[8];
    const float* out_proj_w= (const float*)d_in[9];
    float* out = (float*)d_out;

    float *xz, *xc, *xdbl, *dt, *y;
    cudaGetSymbolAddress((void**)&xz,   g_xz);
    cudaGetSymbolAddress((void**)&xc,   g_xc);
    cudaGetSymbolAddress((void**)&xdbl, g_xdbl);
    cudaGetSymbolAddress((void**)&dt,   g_dt);
    cudaGetSymbolAddress((void**)&y,    g_y);

    // 1) in_proj: xz[4096,4096] = x[4096,1024] * W^T
    {
        dim3 grid(XZ_COLS / 128, M_ROWS / 128);
        sgemm_nt<128, 128, 16, 8, 8, 0><<<grid, 256>>>(
            M_ROWS, XZ_COLS, DMODEL, x, DMODEL, in_proj_w, DMODEL, xz, XZ_COLS, nullptr);
    }

    // 2) depthwise conv + silu -> g_xc
    {
        int n = M_ROWS * DINNER;
        conv_silu_kernel<<<(n + 255) / 256, 256>>>(conv_w, conv_b);
    }

    // 3) x_proj: xdbl[4096,96] = xc[4096,2048] * W^T
    {
        dim3 grid(XDBL_COLS / 32, M_ROWS / 64);
        sgemm_nt<64, 32, 32, 4, 4, 0><<<grid, 128>>>(
            M_ROWS, XDBL_COLS, DINNER, xc, DINNER, x_proj_w, DINNER, xdbl, XDBL_COLS, nullptr);
    }

    // 4) dt_proj + bias + softplus: dt[4096,2048] = softplus(xdbl[:, :64] * W^T + b)
    {
        dim3 grid(DINNER / 64, M_ROWS / 64);
        sgemm_nt<64, 64, 16, 4, 4, 1><<<grid, 256>>>(
            M_ROWS, DINNER, DTRANK, xdbl, XDBL_COLS, dt_proj_w, DTRANK, dt, DINNER, dt_proj_b);
    }

    // 5) selective scan -> g_y
    scan_kernel<<<B_SZ * DINNER / 16, 256>>>(A_log, D_param);

    // 6) gate: y *= silu(z)
    {
        int n = M_ROWS * DINNER;
        gate_kernel<<<(n + 255) / 256, 256>>>();
    }

    // 7) out_proj: out[4096,1024] = y[4096,2048] * W^T
    {
        dim3 grid(DMODEL / 128, M_ROWS / 128);
        sgemm_nt<128, 128, 16, 8, 8, 0><<<grid, 256>>>(
            M_ROWS, DMODEL, DINNER, y, DINNER, out_proj_w, DINNER, out, DMODEL, nullptr);
    }
}

// round 3
// speedup vs baseline: 1.6182x; 1.6182x over previous
#include <cuda_runtime.h>
#include <cuda_bf16.h>
#include <math.h>
#include <stdint.h>

// ---------------------------------------------------------------------------
// Problem constants
// ---------------------------------------------------------------------------
#define B_SZ    2
#define LSEQ    2048
#define DMODEL  1024
#define DINNER  2048
#define DSTATE  16
#define DTRANK  64
#define DCONV   4
#define M_ROWS  (B_SZ * LSEQ)            // 4096
#define XZ_COLS (2 * DINNER)             // 4096
#define XDBL_COLS (DTRANK + 2 * DSTATE)  // 96

// ---------------------------------------------------------------------------
// Scratch (static device allocations: no cudaMalloc allowed)
// ---------------------------------------------------------------------------
__device__ float g_xz  [(size_t)M_ROWS * XZ_COLS];    // in_proj output [4096,4096]
__device__ float g_xc  [(size_t)M_ROWS * DINNER];     // conv+silu     [4096,2048]
__device__ float g_xdbl[(size_t)M_ROWS * XDBL_COLS];  // x_proj output [4096,96]
__device__ float g_dt  [(size_t)M_ROWS * DINNER];     // softplus(dt)  [4096,2048]
__device__ float g_y   [(size_t)M_ROWS * DINNER];     // scan output   [4096,2048]

// split-bf16 operands for the tensor-core GEMMs
__device__ __nv_bfloat16 g_xhi [(size_t)M_ROWS * DMODEL];
__device__ __nv_bfloat16 g_xlo [(size_t)M_ROWS * DMODEL];
__device__ __nv_bfloat16 g_wihi[(size_t)XZ_COLS * DMODEL];
__device__ __nv_bfloat16 g_wilo[(size_t)XZ_COLS * DMODEL];
__device__ __nv_bfloat16 g_yhi [(size_t)M_ROWS * DINNER];
__device__ __nv_bfloat16 g_ylo [(size_t)M_ROWS * DINNER];
__device__ __nv_bfloat16 g_wohi[(size_t)DMODEL * DINNER];
__device__ __nv_bfloat16 g_wolo[(size_t)DMODEL * DINNER];

// ---------------------------------------------------------------------------
// PTX helpers (baseline sm_80+/sm_90 features only — NO tcgen05)
// ---------------------------------------------------------------------------
__device__ __forceinline__ uint32_t smem_u32(const void* p) {
    uint32_t a;
    asm("{ .reg .u64 t; cvta.to.shared.u64 t, %1; cvt.u32.u64 %0, t; }" : "=r"(a) : "l"(p));
    return a;
}
__device__ __forceinline__ void cp_async16(uint32_t saddr, const void* gaddr) {
    asm volatile("cp.async.cg.shared.global [%0], [%1], 16;" :: "r"(saddr), "l"(gaddr));
}
#define CP_COMMIT()  asm volatile("cp.async.commit_group;" ::: "memory")
#define CP_WAIT1()   asm volatile("cp.async.wait_group 1;" ::: "memory")

__device__ __forceinline__ void ldsm_x4(uint32_t (&r)[4], uint32_t addr) {
    asm volatile("ldmatrix.sync.aligned.m8n8.x4.shared.b16 {%0,%1,%2,%3}, [%4];"
        : "=r"(r[0]), "=r"(r[1]), "=r"(r[2]), "=r"(r[3]) : "r"(addr));
}
__device__ __forceinline__ void mma_bf16(float (&d)[4],
                                         const uint32_t (&a)[4],
                                         uint32_t b0, uint32_t b1) {
    asm volatile(
        "mma.sync.aligned.m16n8k16.row.col.f32.bf16.bf16.f32 "
        "{%0,%1,%2,%3}, {%4,%5,%6,%7}, {%8,%9}, {%0,%1,%2,%3};"
        : "+f"(d[0]), "+f"(d[1]), "+f"(d[2]), "+f"(d[3])
        : "r"(a[0]), "r"(a[1]), "r"(a[2]), "r"(a[3]), "r"(b0), "r"(b1));
}

// ---------------------------------------------------------------------------
// Split-bf16 tensor-core GEMM: C[M,N] = A[M,K]*B[N,K]^T (3 hi/lo passes)
// Block tile 128x128, BK=32, 8 warps (warp tile 64x32), cp.async double buffer.
// SMEM tile pitch = 40 bf16 (80B) -> ldmatrix conflict-free.
// ---------------------------------------------------------------------------
#define TCBM 128
#define TCBN 128
#define TCBK 32
#define PITCHB 80                        // bytes per smem row (32 bf16 + pad)
#define OPTILE (TCBM * PITCHB)           // 10240 bytes per operand tile
#define STAGEB (4 * OPTILE)              // Ahi,Alo,Bhi,Blo = 40960
#define TCSMEM (2 * STAGEB)              // 81920

__device__ __forceinline__ void fill_op(uint32_t sbase, const __nv_bfloat16* g,
                                        int grow0, int K, int k0, int tid) {
#pragma unroll
    for (int t = 0; t < 2; t++) {
        int u = tid + t * 256;           // 512 chunks of 16B
        int r = u >> 2, seg = u & 3;
        const __nv_bfloat16* gp = g + (size_t)(grow0 + r) * K + k0 + seg * 8;
        cp_async16(sbase + r * PITCHB + seg * 16, gp);
    }
}

__global__ void __launch_bounds__(256)
tc_gemm_kernel(int K,
               const __nv_bfloat16* __restrict__ Ahi, const __nv_bfloat16* __restrict__ Alo,
               const __nv_bfloat16* __restrict__ Bhi, const __nv_bfloat16* __restrict__ Blo,
               float* __restrict__ C, int ldc)
{
    extern __shared__ char smem[];
    const uint32_t sb = smem_u32(smem);

    const int tid  = threadIdx.x;
    const int lane = tid & 31;
    const int w    = tid >> 5;
    const int wm   = w & 1;              // 2 warps along M (64 each)
    const int wn   = w >> 1;             // 4 warps along N (32 each)
    const int mrow = blockIdx.y * TCBM;
    const int ncol = blockIdx.x * TCBN;

    float acc[4][4][4];                  // [mi][nj][4]
#pragma unroll
    for (int i = 0; i < 4; i++)
#pragma unroll
        for (int j = 0; j < 4; j++)
#pragma unroll
            for (int e = 0; e < 4; e++) acc[i][j][e] = 0.f;

    const int nc = K / TCBK;

    // prologue: fill chunk 0 into buffer 0
    {
        uint32_t s0 = sb;
        fill_op(s0 + 0 * OPTILE, Ahi, mrow, K, 0, tid);
        fill_op(s0 + 1 * OPTILE, Alo, mrow, K, 0, tid);
        fill_op(s0 + 2 * OPTILE, Bhi, ncol, K, 0, tid);
        fill_op(s0 + 3 * OPTILE, Blo, ncol, K, 0, tid);
        CP_COMMIT();
    }

    // ldmatrix lane addressing (constant per thread)
    const int a_row = (lane & 15);
    const int a_cb  = (lane >> 4);            // 0/1 -> k block 16B
    const int b_row = (lane & 7) + ((lane >> 4) << 3);
    const int b_cb  = (lane >> 3) & 1;

    for (int c = 0; c < nc; c++) {
        if (c + 1 < nc) {
            uint32_t s1 = sb + ((c + 1) & 1) * STAGEB;
            int k1 = (c + 1) * TCBK;
            fill_op(s1 + 0 * OPTILE, Ahi, mrow, K, k1, tid);
            fill_op(s1 + 1 * OPTILE, Alo, mrow, K, k1, tid);
            fill_op(s1 + 2 * OPTILE, Bhi, ncol, K, k1, tid);
            fill_op(s1 + 3 * OPTILE, Blo, ncol, K, k1, tid);
        }
        CP_COMMIT();
        CP_WAIT1();
        __syncthreads();

        const uint32_t s = sb + (c & 1) * STAGEB;
        const uint32_t sAhi = s + 0 * OPTILE;
        const uint32_t sAlo = s + 1 * OPTILE;
        const uint32_t sBhi = s + 2 * OPTILE;
        const uint32_t sBlo = s + 3 * OPTILE;

#pragma unroll
        for (int ks = 0; ks < 2; ks++) {
            uint32_t ahi[4][4], alo[4][4];
            uint32_t bhi[2][4], blo[2][4];
#pragma unroll
            for (int mi = 0; mi < 4; mi++) {
                uint32_t ao = (uint32_t)((wm * 64 + mi * 16 + a_row) * PITCHB + ks * 32 + a_cb * 16);
                ldsm_x4(ahi[mi], sAhi + ao);
                ldsm_x4(alo[mi], sAlo + ao);
            }
#pragma unroll
            for (int j = 0; j < 2; j++) {
                uint32_t bo = (uint32_t)((wn * 32 + j * 16 + b_row) * PITCHB + ks * 32 + b_cb * 16);
                ldsm_x4(bhi[j], sBhi + bo);
                ldsm_x4(blo[j], sBlo + bo);
            }
#pragma unroll
            for (int mi = 0; mi < 4; mi++)
#pragma unroll
                for (int nj = 0; nj < 4; nj++) {
                    const int j = nj >> 1, h = (nj & 1) * 2;
                    mma_bf16(acc[mi][nj], ahi[mi], bhi[j][h], bhi[j][h + 1]); // hi*hi
                    mma_bf16(acc[mi][nj], ahi[mi], blo[j][h], blo[j][h + 1]); // hi*lo
                    mma_bf16(acc[mi][nj], alo[mi], bhi[j][h], bhi[j][h + 1]); // lo*hi
                }
        }
        __syncthreads();
    }

    // epilogue: d0,d1 at (row, col..col+1); d2,d3 at (row+8, ...)
    const int er = lane >> 2;
    const int ec = (lane & 3) * 2;
#pragma unroll
    for (int mi = 0; mi < 4; mi++) {
#pragma unroll
        for (int nj = 0; nj < 4; nj++) {
            int r0 = mrow + wm * 64 + mi * 16 + er;
            int cc = ncol + wn * 32 + nj * 8 + ec;
            float2 v0 = make_float2(acc[mi][nj][0], acc[mi][nj][1]);
            float2 v1 = make_float2(acc[mi][nj][2], acc[mi][nj][3]);
            *reinterpret_cast<float2*>(C + (size_t)r0 * ldc + cc) = v0;
            *reinterpret_cast<float2*>(C + (size_t)(r0 + 8) * ldc + cc) = v1;
        }
    }
}

// ---------------------------------------------------------------------------
// fp32 -> (bf16 hi, bf16 lo)
// ---------------------------------------------------------------------------
__global__ void cvt_kernel(const float* __restrict__ in,
                           __nv_bfloat16* __restrict__ hi,
                           __nv_bfloat16* __restrict__ lo, int n)
{
    int i = blockIdx.x * blockDim.x + threadIdx.x;
    if (i >= n) return;
    float v = in[i];
    __nv_bfloat16 h = __float2bfloat16(v);
    hi[i] = h;
    lo[i] = __float2bfloat16(v - __bfloat162float(h));
}

// ---------------------------------------------------------------------------
// Generic NT SGEMM (skinny GEMMs: x_proj, dt_proj)
// ---------------------------------------------------------------------------
template<int BM, int BN, int BK, int TM, int TN, int EPI>
__global__ void sgemm_nt(int M, int N, int K,
                         const float* __restrict__ A, int lda,
                         const float* __restrict__ Bm, int ldb,
                         float* __restrict__ C, int ldc,
                         const float* __restrict__ bias)
{
    constexpr int THREADS = (BM / TM) * (BN / TN);
    __shared__ float As[BK][BM];
    __shared__ float Bs[BK][BN];

    const int tid  = threadIdx.x;
    const int brow = blockIdx.y * BM;
    const int bcol = blockIdx.x * BN;
    const int tcol = tid % (BN / TN);
    const int trow = tid / (BN / TN);

    float acc[TM][TN];
#pragma unroll
    for (int i = 0; i < TM; i++)
#pragma unroll
        for (int j = 0; j < TN; j++) acc[i][j] = 0.f;

    constexpr int AV = (BM * BK) / (4 * THREADS);
    constexpr int BV = (BN * BK) / (4 * THREADS);
    constexpr int ROWS_PER_PASS = (THREADS * 4) / BK;
    const int l_r = (tid * 4) / BK;
    const int l_c = (tid * 4) % BK;

    for (int k0 = 0; k0 < K; k0 += BK) {
#pragma unroll
        for (int v = 0; v < AV; v++) {
            int r = l_r + v * ROWS_PER_PASS;
            float4 f = *reinterpret_cast<const float4*>(
                &A[(size_t)(brow + r) * lda + k0 + l_c]);
            As[l_c + 0][r] = f.x; As[l_c + 1][r] = f.y;
            As[l_c + 2][r] = f.z; As[l_c + 3][r] = f.w;
        }
#pragma unroll
        for (int v = 0; v < BV; v++) {
            int r = l_r + v * ROWS_PER_PASS;
            float4 f = *reinterpret_cast<const float4*>(
                &Bm[(size_t)(bcol + r) * ldb + k0 + l_c]);
            Bs[l_c + 0][r] = f.x; Bs[l_c + 1][r] = f.y;
            Bs[l_c + 2][r] = f.z; Bs[l_c + 3][r] = f.w;
        }
        __syncthreads();

#pragma unroll
        for (int k = 0; k < BK; k++) {
            float ar[TM], br[TN];
#pragma unroll
            for (int i = 0; i < TM; i++) ar[i] = As[k][trow * TM + i];
#pragma unroll
            for (int j = 0; j < TN; j++) br[j] = Bs[k][tcol * TN + j];
#pragma unroll
            for (int i = 0; i < TM; i++)
#pragma unroll
                for (int j = 0; j < TN; j++)
                    acc[i][j] += ar[i] * br[j];
        }
        __syncthreads();
    }

#pragma unroll
    for (int i = 0; i < TM; i++) {
        int r = brow + trow * TM + i;
#pragma unroll
        for (int j = 0; j < TN; j++) {
            int c = bcol + tcol * TN + j;
            float v = acc[i][j];
            if (EPI == 1) {
                v += bias[c];
                v = (v > 20.f) ? v : log1pf(__expf(v));
            }
            C[(size_t)r * ldc + c] = v;
        }
    }
}

// ---------------------------------------------------------------------------
// Depthwise causal conv1d (taps=4) + bias + SiLU
// ---------------------------------------------------------------------------
__global__ void conv_silu_kernel(const float* __restrict__ conv_w,
                                 const float* __restrict__ conv_b)
{
    int idx = blockIdx.x * blockDim.x + threadIdx.x;
    if (idx >= M_ROWS * DINNER) return;
    int d = idx % DINNER;
    int m = idx / DINNER;
    int t = m % LSEQ;
    int b = m / LSEQ;

    float acc = conv_b[d];
#pragma unroll
    for (int j = 0; j < DCONV; j++) {
        int tt = t - (DCONV - 1) + j;
        if (tt >= 0)
            acc += g_xz[(size_t)(b * LSEQ + tt) * XZ_COLS + d] * conv_w[d * DCONV + j];
    }
    float s = 1.f / (1.f + __expf(-acc));
    g_xc[(size_t)m * DINNER + d] = acc * s;
}

// ---------------------------------------------------------------------------
// Selective scan (16 lanes per channel)
// ---------------------------------------------------------------------------
__global__ void scan_kernel(const float* __restrict__ A_log,
                            const float* __restrict__ D_param)
{
    const int lane16 = threadIdx.x & 15;
    const int grp    = threadIdx.x >> 4;
    const int chunk  = blockIdx.x;
    const int b      = chunk / (DINNER / 16);
    const int d      = (chunk % (DINNER / 16)) * 16 + grp;

    const float Ad = -__expf(A_log[d * DSTATE + lane16]);
    const float Dd = D_param[d];

    const float* dt_p = g_dt   + (size_t)b * LSEQ * DINNER + d;
    const float* x_p  = g_xc   + (size_t)b * LSEQ * DINNER + d;
    const float* bc_p = g_xdbl + (size_t)b * LSEQ * XDBL_COLS;
    float*       y_p  = g_y    + (size_t)b * LSEQ * DINNER + d;

    float h = 0.f;
    float dtv = dt_p[0];
    float xv  = x_p[0];
    float Bv  = bc_p[DTRANK + lane16];
    float Cv  = bc_p[DTRANK + DSTATE + lane16];

    for (int t = 0; t < LSEQ; t++) {
        float ndt = 0.f, nx = 0.f, nB = 0.f, nC = 0.f;
        if (t + 1 < LSEQ) {
            ndt = dt_p[(size_t)(t + 1) * DINNER];
            nx  = x_p [(size_t)(t + 1) * DINNER];
            nB  = bc_p[(size_t)(t + 1) * XDBL_COLS + DTRANK + lane16];
            nC  = bc_p[(size_t)(t + 1) * XDBL_COLS + DTRANK + DSTATE + lane16];
        }
        float dA = __expf(dtv * Ad);
        h = dA * h + (dtv * xv) * Bv;
        float p = h * Cv;
        p += __shfl_xor_sync(0xffffffffu, p, 1);
        p += __shfl_xor_sync(0xffffffffu, p, 2);
        p += __shfl_xor_sync(0xffffffffu, p, 4);
        p += __shfl_xor_sync(0xffffffffu, p, 8);
        if (lane16 == 0)
            y_p[(size_t)t * DINNER] = p + Dd * xv;
        dtv = ndt; xv = nx; Bv = nB; Cv = nC;
    }
}

// ---------------------------------------------------------------------------
// Gate + split-bf16 convert: yhi/ylo = split( y * silu(z) )
// ---------------------------------------------------------------------------
__global__ void gate_cvt_kernel()
{
    int idx = blockIdx.x * blockDim.x + threadIdx.x;
    if (idx >= M_ROWS * DINNER) return;
    int d = idx % DINNER;
    int m = idx / DINNER;
    float z = g_xz[(size_t)m * XZ_COLS + DINNER + d];
    float s = z / (1.f + __expf(-z));
    float v = g_y[(size_t)m * DINNER + d] * s;
    __nv_bfloat16 h = __float2bfloat16(v);
    g_yhi[(size_t)m * DINNER + d] = h;
    g_ylo[(size_t)m * DINNER + d] = __float2bfloat16(v - __bfloat162float(h));
}

// ---------------------------------------------------------------------------
// Launch
// ---------------------------------------------------------------------------
extern "C" void kernel_launch(void* const* d_in, const int* in_sizes, int n_in,
                              void* d_out, int out_size)
{
    const float* x         = (const float*)d_in[0];
    const float* in_proj_w = (const float*)d_in[1];
    const float* conv_w    = (const float*)d_in[2];
    const float* conv_b    = (const float*)d_in[3];
    const float* x_proj_w  = (const float*)d_in[4];
    const float* dt_proj_w = (const float*)d_in[5];
    const float* dt_proj_b = (const float*)d_in[6];
    const float* A_log     = (const float*)d_in[7];
    const float* D_param   = (const float*)d_in[8];
    const float* out_proj_w= (const float*)d_in[9];
    float* out = (float*)d_out;

    float *xz, *xc, *xdbl, *dt;
    cudaGetSymbolAddress((void**)&xz,   g_xz);
    cudaGetSymbolAddress((void**)&xc,   g_xc);
    cudaGetSymbolAddress((void**)&xdbl, g_xdbl);
    cudaGetSymbolAddress((void**)&dt,   g_dt);
    __nv_bfloat16 *xhi, *xlo, *wihi, *wilo, *yhi, *ylo, *wohi, *wolo;
    cudaGetSymbolAddress((void**)&xhi,  g_xhi);
    cudaGetSymbolAddress((void**)&xlo,  g_xlo);
    cudaGetSymbolAddress((void**)&wihi, g_wihi);
    cudaGetSymbolAddress((void**)&wilo, g_wilo);
    cudaGetSymbolAddress((void**)&yhi,  g_yhi);
    cudaGetSymbolAddress((void**)&ylo,  g_ylo);
    cudaGetSymbolAddress((void**)&wohi, g_wohi);
    cudaGetSymbolAddress((void**)&wolo, g_wolo);

    cudaFuncSetAttribute(tc_gemm_kernel, cudaFuncAttributeMaxDynamicSharedMemorySize, TCSMEM);

    // 0) split-bf16 conversions
    {
        int n = M_ROWS * DMODEL;
        cvt_kernel<<<(n + 255) / 256, 256>>>(x, xhi, xlo, n);
        n = XZ_COLS * DMODEL;
        cvt_kernel<<<(n + 255) / 256, 256>>>(in_proj_w, wihi, wilo, n);
        n = DMODEL * DINNER;
        cvt_kernel<<<(n + 255) / 256, 256>>>(out_proj_w, wohi, wolo, n);
    }

    // 1) in_proj: xz[4096,4096] = x * W^T  (mma.sync split-bf16)
    {
        dim3 grid(XZ_COLS / TCBN, M_ROWS / TCBM);   // 32 x 32
        tc_gemm_kernel<<<grid, 256, TCSMEM>>>(DMODEL, xhi, xlo, wihi, wilo, xz, XZ_COLS);
    }

    // 2) depthwise conv + silu -> g_xc
    {
        int n = M_ROWS * DINNER;
        conv_silu_kernel<<<(n + 255) / 256, 256>>>(conv_w, conv_b);
    }

    // 3) x_proj: xdbl[4096,96] = xc * W^T
    {
        dim3 grid(XDBL_COLS / 32, M_ROWS / 64);
        sgemm_nt<64, 32, 32, 4, 4, 0><<<grid, 128>>>(
            M_ROWS, XDBL_COLS, DINNER, xc, DINNER, x_proj_w, DINNER, xdbl, XDBL_COLS, nullptr);
    }

    // 4) dt_proj + bias + softplus
    {
        dim3 grid(DINNER / 64, M_ROWS / 64);
        sgemm_nt<64, 64, 16, 4, 4, 1><<<grid, 256>>>(
            M_ROWS, DINNER, DTRANK, xdbl, XDBL_COLS, dt_proj_w, DTRANK, dt, DINNER, dt_proj_b);
    }

    // 5) selective scan -> g_y
    scan_kernel<<<B_SZ * DINNER / 16, 256>>>(A_log, D_param);

    // 6) gate + split-bf16 convert -> yhi/ylo
    {
        int n = M_ROWS * DINNER;
        gate_cvt_kernel<<<(n + 255) / 256, 256>>>();
    }

    // 7) out_proj: out[4096,1024] = y * W^T  (mma.sync split-bf16)
    {
        dim3 grid(DMODEL / TCBN, M_ROWS / TCBM);    // 8 x 32
        tc_gemm_kernel<<<grid, 256, TCSMEM>>>(DINNER, yhi, ylo, wohi, wolo, out, DMODEL);
    }
}